// round 2
// baseline (speedup 1.0000x reference)
#include <cuda_runtime.h>

#define NPIX 4096
#define CC   256
#define CQ   64
#define BB   8
#define ROWS_ALL (2*CQ + CC)   // 384: [q(64) | k(64) | gamma-folded value(256)]

// ---- scratch (device globals; no runtime allocation allowed) ----
__device__ float g_Q  [BB*CQ*NPIX];          // [b][cq][n]
__device__ float g_K  [BB*CQ*NPIX];          // [b][cq][m]
__device__ float g_VG [(size_t)BB*CC*NPIX];  // [b][c][n], gamma pre-folded
__device__ float g_Wall[ROWS_ALL*CC];
__device__ float g_ball[ROWS_ALL];

// ============================================================
// Kernel 0: build combined weight matrix.
//   rows [0,64)    = Wq, bias bq
//   rows [64,128)  = Wk, bias bk
//   rows [128,384) = Wg@Wv, bias Wg@bv   (gamma folded into V)
// ============================================================
__global__ void build_weights(const float* __restrict__ qw, const float* __restrict__ qb,
                              const float* __restrict__ kw, const float* __restrict__ kb,
                              const float* __restrict__ vw, const float* __restrict__ vb,
                              const float* __restrict__ gw) {
    int r = blockIdx.x;      // 0..383
    int d = threadIdx.x;     // 0..255
    if (r < CQ) {
        g_Wall[r*CC + d] = qw[r*CC + d];
        if (d == 0) g_ball[r] = qb[r];
    } else if (r < 2*CQ) {
        int rr = r - CQ;
        g_Wall[r*CC + d] = kw[rr*CC + d];
        if (d == 0) g_ball[r] = kb[rr];
    } else {
        int c = r - 2*CQ;
        float acc = 0.f;
        for (int cp = 0; cp < CC; ++cp)
            acc = fmaf(gw[c*CC + cp], vw[cp*CC + d], acc);
        g_Wall[r*CC + d] = acc;
        if (d == 0) {
            float bacc = 0.f;
            for (int cp = 0; cp < CC; ++cp)
                bacc = fmaf(gw[c*CC + cp], vb[cp], bacc);
            g_ball[r] = bacc;
        }
    }
}

// ============================================================
// Kernel 1: projection GEMM. out[384, 4096] per batch = Wall @ x[b]
// grid (n_tiles=64, co_tiles=6, B=8), block 256 threads, tile 64co x 64n,
// each thread 4x4 register tile (strided).
// ============================================================
__global__ void __launch_bounds__(256) proj_kernel(const float* __restrict__ x) {
    __shared__ float Ws[16][64];   // [k][co]
    __shared__ float Xs[16][64];   // [k][n]
    int b   = blockIdx.z;
    int co0 = blockIdx.y * 64;
    int n0  = blockIdx.x * 64;
    int t   = threadIdx.x;
    int tn  = t % 16;
    int tco = t / 16;
    const float* xb = x + (size_t)b * CC * NPIX;

    float acc[4][4];
    #pragma unroll
    for (int i = 0; i < 4; i++)
        #pragma unroll
        for (int j = 0; j < 4; j++) acc[i][j] = 0.f;

    for (int k0 = 0; k0 < CC; k0 += 16) {
        {   // Ws[k][co] = Wall[(co0+co)][k0+k]
            int k  = t % 16;
            int co = t / 16;
            #pragma unroll
            for (int i = 0; i < 4; i++)
                Ws[k][co + 16*i] = g_Wall[(co0 + co + 16*i)*CC + k0 + k];
        }
        {   // Xs[k][n] (float4 along n)
            int idx = t * 4;
            int k = idx / 64, n = idx % 64;
            float4 v = *(const float4*)&xb[(size_t)(k0 + k)*NPIX + n0 + n];
            *(float4*)&Xs[k][n] = v;
        }
        __syncthreads();
        #pragma unroll
        for (int k = 0; k < 16; k++) {
            float a[4], bx[4];
            #pragma unroll
            for (int i = 0; i < 4; i++) a[i]  = Ws[k][tco + 16*i];
            #pragma unroll
            for (int j = 0; j < 4; j++) bx[j] = Xs[k][tn + 16*j];
            #pragma unroll
            for (int i = 0; i < 4; i++)
                #pragma unroll
                for (int j = 0; j < 4; j++)
                    acc[i][j] = fmaf(a[i], bx[j], acc[i][j]);
        }
        __syncthreads();
    }

    #pragma unroll
    for (int i = 0; i < 4; i++) {
        int co = co0 + tco + 16*i;
        float bias = g_ball[co];
        float* dst;
        if (co < CQ)          dst = g_Q  + ((size_t)b*CQ + co)        * NPIX;
        else if (co < 2*CQ)   dst = g_K  + ((size_t)b*CQ + (co-CQ))   * NPIX;
        else                  dst = g_VG + ((size_t)b*CC + (co-2*CQ)) * NPIX;
        #pragma unroll
        for (int j = 0; j < 4; j++)
            dst[n0 + tn + 16*j] = acc[i][j] + bias;
    }
}

// ============================================================
// Kernel 2: fused attention.
//   out[b,c,m] = bg[c] + sum_n VG[b,c,n] * elu(Q[:,n] . K[:,m]) / N
// grid (m_tiles=64, B=8), block 256 threads.
// Output tile per block: [256 c x 64 m].
// Per n-tile (64): phase1 S[n][m] via Q^T K (16x16 threads, 4x4 each),
//                  phase2 O += VG_chunk @ S   (32x8 threads, 8x8 each).
// smem = Ks(16K) + Ss(16K) + U(16K, union of Qs / VG chunk) = 48KB static.
// ============================================================
__global__ void __launch_bounds__(256) attn_kernel(float* __restrict__ out,
                                                   const float* __restrict__ gbias) {
    __shared__ float Ks[64][64];   // [cq][m]   (persistent for the block)
    __shared__ float Ss[64][64];   // [m][n]    (transposed so phase2 reads broadcast)
    __shared__ float U[4096];      // phase1: Qs[cq*64+n]; phase2: VGs[nn*256+c]

    int b  = blockIdx.y;
    int m0 = blockIdx.x * 64;
    int t  = threadIdx.x;

    // load K tile once
    {
        int idx = t * 4;
        #pragma unroll
        for (int r = 0; r < 4; r++) {
            int id = idx + r * 1024;
            int cq = id / 64, m = id % 64;
            *(float4*)&Ks[cq][m] =
                *(const float4*)&g_K[((size_t)b*CQ + cq)*NPIX + m0 + m];
        }
    }

    float acc[8][8];
    #pragma unroll
    for (int i = 0; i < 8; i++)
        #pragma unroll
        for (int j = 0; j < 8; j++) acc[i][j] = 0.f;

    const int t16x = t % 16, t16y = t / 16;  // phase1: n-dir, m-dir
    const int tc   = t % 32, tm8  = t / 32;  // phase2: c-dir, m-dir

    for (int it = 0; it < 64; ++it) {
        int n0 = it * 64;
        __syncthreads();                       // U free (prev phase2 done); Ks ready (it==0)
        {   // load Q tile into U: Qs[cq][n]
            int idx = t * 4;
            #pragma unroll
            for (int r = 0; r < 4; r++) {
                int id = idx + r * 1024;
                int cq = id / 64, n = id % 64;
                *(float4*)&U[cq*64 + n] =
                    *(const float4*)&g_Q[((size_t)b*CQ + cq)*NPIX + n0 + n];
            }
        }
        __syncthreads();

        // ---- phase 1: S = Q^T K, elu, /N ----
        float s[4][4];
        #pragma unroll
        for (int i = 0; i < 4; i++)
            #pragma unroll
            for (int j = 0; j < 4; j++) s[i][j] = 0.f;

        #pragma unroll 8
        for (int cq = 0; cq < 64; cq++) {
            float qv[4], kv[4];
            #pragma unroll
            for (int i = 0; i < 4; i++) qv[i] = U[cq*64 + t16x + 16*i];
            #pragma unroll
            for (int j = 0; j < 4; j++) kv[j] = Ks[cq][t16y + 16*j];
            #pragma unroll
            for (int i = 0; i < 4; i++)
                #pragma unroll
                for (int j = 0; j < 4; j++)
                    s[i][j] = fmaf(qv[i], kv[j], s[i][j]);
        }
        #pragma unroll
        for (int i = 0; i < 4; i++)
            #pragma unroll
            for (int j = 0; j < 4; j++) {
                float v = s[i][j];
                v = (v > 0.f) ? v : (__expf(v) - 1.f);
                Ss[t16y + 16*j][t16x + 16*i] = v * (1.0f / 4096.0f);
            }

        // ---- phase 2: O += VG @ S, VG staged 16 n at a time through U ----
        #pragma unroll 1
        for (int ch = 0; ch < 4; ++ch) {
            __syncthreads();   // ch==0: Ss written & phase1 done with U; else prev chunk consumed
            {   // VGs[nn][c] for nn in [0,16): each thread owns one c row
                int c = t;
                const float* src = &g_VG[((size_t)b*CC + c)*NPIX + n0 + ch*16];
                #pragma unroll
                for (int r = 0; r < 4; r++) {
                    float4 v = *(const float4*)&src[r*4];
                    U[(r*4+0)*256 + c] = v.x;
                    U[(r*4+1)*256 + c] = v.y;
                    U[(r*4+2)*256 + c] = v.z;
                    U[(r*4+3)*256 + c] = v.w;
                }
            }
            __syncthreads();
            #pragma unroll
            for (int nn = 0; nn < 16; ++nn) {
                float sv[8], vv[8];
                #pragma unroll
                for (int j = 0; j < 8; j++) sv[j] = Ss[tm8 + 8*j][ch*16 + nn]; // broadcast
                #pragma unroll
                for (int i = 0; i < 8; i++) vv[i] = U[nn*256 + tc + 32*i];    // conflict-free
                #pragma unroll
                for (int i = 0; i < 8; i++)
                    #pragma unroll
                    for (int j = 0; j < 8; j++)
                        acc[i][j] = fmaf(vv[i], sv[j], acc[i][j]);
            }
        }
    }

    // ---- epilogue: stage through Ss for coalesced float4 stores; add gamma bias ----
    for (int p = 0; p < 4; p++) {
        __syncthreads();
        #pragma unroll
        for (int ii = 0; ii < 2; ++ii) {
            int i = 2*p + ii;
            int c_in = tc + 32*ii;           // local c within [0,64)
            #pragma unroll
            for (int j = 0; j < 8; j++)
                Ss[c_in][tm8 + 8*j] = acc[i][j];
        }
        __syncthreads();
        {
            int idx = t * 4;
            #pragma unroll
            for (int r = 0; r < 4; r++) {
                int id = idx + r * 1024;
                int cc = id / 64, m = id % 64;
                int cg = 64*p + cc;
                float bias = gbias[cg];
                float4 v = *(float4*)&Ss[cc][m];
                v.x += bias; v.y += bias; v.z += bias; v.w += bias;
                *(float4*)&out[((size_t)b*CC + cg)*NPIX + m0 + m] = v;
            }
        }
    }
}

// ============================================================
extern "C" void kernel_launch(void* const* d_in, const int* in_sizes, int n_in,
                              void* d_out, int out_size) {
    const float* x  = (const float*)d_in[0];
    const float* qw = (const float*)d_in[1];
    const float* qb = (const float*)d_in[2];
    const float* kw = (const float*)d_in[3];
    const float* kb = (const float*)d_in[4];
    const float* vw = (const float*)d_in[5];
    const float* vb = (const float*)d_in[6];
    const float* gw = (const float*)d_in[7];
    const float* gb = (const float*)d_in[8];
    float* out = (float*)d_out;

    build_weights<<<ROWS_ALL, 256>>>(qw, qb, kw, kb, vw, vb, gw);
    proj_kernel<<<dim3(64, 6, BB), 256>>>(x);
    attn_kernel<<<dim3(64, BB), 256>>>(out, gb);
}

// round 3
// speedup vs baseline: 1.0220x; 1.0220x over previous
#include <cuda_runtime.h>

#define NPIX 4096
#define CC   256
#define CQ   64
#define BB   8
#define ROWS_ALL (2*CQ + CC)   // 384: [q(64) | k(64) | gamma-folded value(256)]

typedef unsigned long long u64;

// ---- packed f32x2 helpers (SASS FFMA2 path; ptxas never emits from C++) ----
__device__ __forceinline__ u64 pack2(float x, float y) {
    u64 r; asm("mov.b64 %0, {%1, %2};" : "=l"(r) : "f"(x), "f"(y)); return r;
}
__device__ __forceinline__ u64 dup2(float x) { return pack2(x, x); }
__device__ __forceinline__ void fma2(u64 &d, u64 a, u64 b) {
    asm("fma.rn.f32x2 %0, %1, %2, %0;" : "+l"(d) : "l"(a), "l"(b));
}
__device__ __forceinline__ float2 unpk(u64 v) {
    float2 f; asm("mov.b64 {%0, %1}, %2;" : "=f"(f.x), "=f"(f.y) : "l"(v)); return f;
}

// ---- scratch (device globals; no runtime allocation allowed) ----
__device__ float g_Q  [BB*CQ*NPIX];          // [b][cq][n]
__device__ float g_K  [BB*CQ*NPIX];          // [b][cq][m]
__device__ float g_VG [(size_t)BB*CC*NPIX];  // [b][c][n], gamma pre-folded
__device__ float g_Wall[ROWS_ALL*CC];
__device__ float g_ball[ROWS_ALL];

// ============================================================
// Kernel 0: build combined weight matrix (gamma folded into V).
// ============================================================
__global__ void build_weights(const float* __restrict__ qw, const float* __restrict__ qb,
                              const float* __restrict__ kw, const float* __restrict__ kb,
                              const float* __restrict__ vw, const float* __restrict__ vb,
                              const float* __restrict__ gw) {
    int r = blockIdx.x;      // 0..383
    int d = threadIdx.x;     // 0..255
    if (r < CQ) {
        g_Wall[r*CC + d] = qw[r*CC + d];
        if (d == 0) g_ball[r] = qb[r];
    } else if (r < 2*CQ) {
        int rr = r - CQ;
        g_Wall[r*CC + d] = kw[rr*CC + d];
        if (d == 0) g_ball[r] = kb[rr];
    } else {
        int c = r - 2*CQ;
        float acc = 0.f;
        for (int cp = 0; cp < CC; ++cp)
            acc = fmaf(gw[c*CC + cp], vw[cp*CC + d], acc);
        g_Wall[r*CC + d] = acc;
        if (d == 0) {
            float bacc = 0.f;
            for (int cp = 0; cp < CC; ++cp)
                bacc = fmaf(gw[c*CC + cp], vb[cp], bacc);
            g_ball[r] = bacc;
        }
    }
}

// ============================================================
// Kernel 1: projection GEMM (packed f32x2). out[384,4096]/batch = Wall @ x[b]
// block 256 threads, tile 64co x 64n, thread 4co x (2x2 packed n).
// ============================================================
__global__ void __launch_bounds__(256) proj_kernel(const float* __restrict__ x) {
    __shared__ float Ws[16][64];   // [k][co]
    __shared__ float Xs[16][64];   // [k][n]
    int b   = blockIdx.z;
    int co0 = blockIdx.y * 64;
    int n0  = blockIdx.x * 64;
    int t   = threadIdx.x;
    int tn  = t % 16;
    int tco = t / 16;
    const float* xb = x + (size_t)b * CC * NPIX;

    u64 acc2[4][2];
    #pragma unroll
    for (int i = 0; i < 4; i++)
        #pragma unroll
        for (int j = 0; j < 2; j++) acc2[i][j] = 0ull;

    for (int k0 = 0; k0 < CC; k0 += 16) {
        {   // Ws[k][co] = Wall[(co0+co)][k0+k]
            int k  = t % 16;
            int co = t / 16;
            #pragma unroll
            for (int i = 0; i < 4; i++)
                Ws[k][co + 16*i] = g_Wall[(co0 + co + 16*i)*CC + k0 + k];
        }
        {   // Xs[k][n] (float4 along n)
            int idx = t * 4;
            int k = idx / 64, n = idx % 64;
            float4 v = *(const float4*)&xb[(size_t)(k0 + k)*NPIX + n0 + n];
            *(float4*)&Xs[k][n] = v;
        }
        __syncthreads();
        #pragma unroll
        for (int k = 0; k < 16; k++) {
            u64 ad[4], bx2[2];
            #pragma unroll
            for (int i = 0; i < 4; i++) ad[i] = dup2(Ws[k][tco + 16*i]);
            #pragma unroll
            for (int j = 0; j < 2; j++) bx2[j] = *(const u64*)&Xs[k][2*tn + 32*j];
            #pragma unroll
            for (int i = 0; i < 4; i++)
                #pragma unroll
                for (int j = 0; j < 2; j++)
                    fma2(acc2[i][j], ad[i], bx2[j]);
        }
        __syncthreads();
    }

    #pragma unroll
    for (int i = 0; i < 4; i++) {
        int co = co0 + tco + 16*i;
        float bias = g_ball[co];
        float* dst;
        if (co < CQ)          dst = g_Q  + ((size_t)b*CQ + co)        * NPIX;
        else if (co < 2*CQ)   dst = g_K  + ((size_t)b*CQ + (co-CQ))   * NPIX;
        else                  dst = g_VG + ((size_t)b*CC + (co-2*CQ)) * NPIX;
        #pragma unroll
        for (int j = 0; j < 2; j++) {
            float2 v = unpk(acc2[i][j]);
            v.x += bias; v.y += bias;
            *(float2*)&dst[n0 + 2*tn + 32*j] = v;
        }
    }
}

// ============================================================
// Kernel 2: fused attention (packed f32x2).
//   out[b,c,m] = bg[c] + sum_n VG[b,c,n] * elu(Q[:,n] . K[:,m]) / N
// grid (64 m-tiles, B=8), 256 threads; output tile [256c x 64m].
// ============================================================
__global__ void __launch_bounds__(256) attn_kernel(float* __restrict__ out,
                                                   const float* __restrict__ gbias) {
    __shared__ float Ks[64][64];   // [cq][m]   (persistent)
    __shared__ float Ss[64][64];   // [m][n]
    __shared__ float U[4096];      // phase1: Qs[cq*64+n]; phase2: VGs[nn*256+c]

    int b  = blockIdx.y;
    int m0 = blockIdx.x * 64;
    int t  = threadIdx.x;

    {   // load K tile once
        int idx = t * 4;
        #pragma unroll
        for (int r = 0; r < 4; r++) {
            int id = idx + r * 1024;
            int cq = id / 64, m = id % 64;
            *(float4*)&Ks[cq][m] =
                *(const float4*)&g_K[((size_t)b*CQ + cq)*NPIX + m0 + m];
        }
    }

    u64 acc2[4][8];   // c-pair (2tc+64*i2, +1) x m (tm8+8*j)
    #pragma unroll
    for (int i = 0; i < 4; i++)
        #pragma unroll
        for (int j = 0; j < 8; j++) acc2[i][j] = 0ull;

    const int t16x = t % 16, t16y = t / 16;  // phase1: n-dir (packed), m-dir
    const int tc   = t % 32, tm8  = t / 32;  // phase2: c-dir (packed), m-dir

    for (int it = 0; it < 64; ++it) {
        int n0 = it * 64;
        __syncthreads();                       // U free
        {   // load Q tile into U: Qs[cq][n]
            int idx = t * 4;
            #pragma unroll
            for (int r = 0; r < 4; r++) {
                int id = idx + r * 1024;
                int cq = id / 64, n = id % 64;
                *(float4*)&U[cq*64 + n] =
                    *(const float4*)&g_Q[((size_t)b*CQ + cq)*NPIX + n0 + n];
            }
        }
        __syncthreads();

        // ---- phase 1: S = Q^T K, elu, /N.  n = 2*t16x + 32*i2 + lane, m = t16y + 16*j
        u64 s2[2][4];
        #pragma unroll
        for (int i = 0; i < 2; i++)
            #pragma unroll
            for (int j = 0; j < 4; j++) s2[i][j] = 0ull;

        #pragma unroll 8
        for (int cq = 0; cq < 64; cq++) {
            u64 qv2[2], kvd[4];
            #pragma unroll
            for (int i = 0; i < 2; i++) qv2[i] = *(const u64*)&U[cq*64 + 2*t16x + 32*i];
            #pragma unroll
            for (int j = 0; j < 4; j++) kvd[j] = dup2(Ks[cq][t16y + 16*j]);
            #pragma unroll
            for (int i = 0; i < 2; i++)
                #pragma unroll
                for (int j = 0; j < 4; j++)
                    fma2(s2[i][j], qv2[i], kvd[j]);
        }
        #pragma unroll
        for (int i = 0; i < 2; i++)
            #pragma unroll
            for (int j = 0; j < 4; j++) {
                float2 v = unpk(s2[i][j]);
                v.x = ((v.x > 0.f) ? v.x : (__expf(v.x) - 1.f)) * (1.0f/4096.0f);
                v.y = ((v.y > 0.f) ? v.y : (__expf(v.y) - 1.f)) * (1.0f/4096.0f);
                *(float2*)&Ss[t16y + 16*j][2*t16x + 32*i] = v;
            }

        // ---- phase 2: O += VG @ S, VG staged 16 n at a time through U ----
        #pragma unroll 1
        for (int ch = 0; ch < 4; ++ch) {
            __syncthreads();
            {   // VGs[nn][c]: each thread owns one c row
                int c = t;
                const float* src = &g_VG[((size_t)b*CC + c)*NPIX + n0 + ch*16];
                #pragma unroll
                for (int r = 0; r < 4; r++) {
                    float4 v = *(const float4*)&src[r*4];
                    U[(r*4+0)*256 + c] = v.x;
                    U[(r*4+1)*256 + c] = v.y;
                    U[(r*4+2)*256 + c] = v.z;
                    U[(r*4+3)*256 + c] = v.w;
                }
            }
            __syncthreads();
            #pragma unroll
            for (int nn = 0; nn < 16; ++nn) {
                u64 vv2[4], svd[8];
                #pragma unroll
                for (int i = 0; i < 4; i++)
                    vv2[i] = *(const u64*)&U[nn*256 + 2*tc + 64*i];       // contiguous c pair
                #pragma unroll
                for (int j = 0; j < 8; j++)
                    svd[j] = dup2(Ss[tm8 + 8*j][ch*16 + nn]);             // broadcast
                #pragma unroll
                for (int i = 0; i < 4; i++)
                    #pragma unroll
                    for (int j = 0; j < 8; j++)
                        fma2(acc2[i][j], vv2[i], svd[j]);
            }
        }
    }

    // ---- epilogue: stage through Ss, add gamma bias, float4 stores ----
    for (int p = 0; p < 4; p++) {   // c block [64p, 64p+64); thread's pair = i2 == p
        __syncthreads();
        #pragma unroll
        for (int j = 0; j < 8; j++) {
            float2 v = unpk(acc2[p][j]);
            Ss[2*tc  ][tm8 + 8*j] = v.x;
            Ss[2*tc+1][tm8 + 8*j] = v.y;
        }
        __syncthreads();
        {
            int idx = t * 4;
            #pragma unroll
            for (int r = 0; r < 4; r++) {
                int id = idx + r * 1024;
                int cc = id / 64, m = id % 64;
                int cg = 64*p + cc;
                float bias = gbias[cg];
                float4 v = *(float4*)&Ss[cc][m];
                v.x += bias; v.y += bias; v.z += bias; v.w += bias;
                *(float4*)&out[((size_t)b*CC + cg)*NPIX + m0 + m] = v;
            }
        }
    }
}

// ============================================================
extern "C" void kernel_launch(void* const* d_in, const int* in_sizes, int n_in,
                              void* d_out, int out_size) {
    const float* x  = (const float*)d_in[0];
    const float* qw = (const float*)d_in[1];
    const float* qb = (const float*)d_in[2];
    const float* kw = (const float*)d_in[3];
    const float* kb = (const float*)d_in[4];
    const float* vw = (const float*)d_in[5];
    const float* vb = (const float*)d_in[6];
    const float* gw = (const float*)d_in[7];
    const float* gb = (const float*)d_in[8];
    float* out = (float*)d_out;

    build_weights<<<ROWS_ALL, 256>>>(qw, qb, kw, kb, vw, vb, gw);
    proj_kernel<<<dim3(64, 6, BB), 256>>>(x);
    attn_kernel<<<dim3(64, BB), 256>>>(out, gb);
}